// round 7
// baseline (speedup 1.0000x reference)
#include <cuda_runtime.h>
#include <cuda_bf16.h>
#include <math.h>
#include <stdint.h>

#define BB 32
#define HH 512
#define VOCAB 50257
#define VPAD  50432          // multiple of 256
#define NB8   (VPAD/8)       // 6304 fragment columns (V1)
#define NBLK  (VPAD/256)     // 197 big-gemm blocks
#define NBP   208            // padded partial stride

// ---------------- device scratch ----------------
// A-fragment buffers: [hl=2][ks=32][m=2][lane=32] uint4 (64KB each)
__device__ uint4 g_XF [2 * 32 * 2 * 32];       // x_cur frags
__device__ uint4 g_H0F[2][2 * 32 * 2 * 32];    // h0 frags, double buffered
__device__ uint4 g_AF [2][2 * 32 * 2 * 32];    // h1 frags, double buffered
__device__ uint4 g_X1F[2 * 32 * 2 * 32];       // x1 frags
// weight fragments: 5 matrices x [ks=32][n8=64][lane=32] uint4 (1MB each)
__device__ uint4 g_WF[(long)5 * 32 * 64 * 32];
__device__ uint4 g_Bf[(long)32 * NB8 * 32];    // V1 frags (103MB)
__device__ float g_c1p[VPAD];
__device__ float g_e0[BB * HH];                // exp(logits0)
__device__ float g_ps0[BB * 64];               // layer-0 softmax partial sums
__device__ float g_E[BB * VPAD];               // exp(logits1)
__device__ float g_psum[BB * NBP];
__device__ float g_pmax[BB * NBP];
__device__ int   g_pidx[BB * NBP];
__device__ float g_invS[BB];

// ---------------- helpers ----------------
__device__ __forceinline__ uint32_t pk_bf2(float a, float b) {
    uint32_t ua = (uint32_t)__bfloat16_as_ushort(__float2bfloat16_rn(a));
    uint32_t ub = (uint32_t)__bfloat16_as_ushort(__float2bfloat16_rn(b));
    return ua | (ub << 16);
}
__device__ __forceinline__ float bf_hi(float v) {
    return __bfloat162float(__float2bfloat16_rn(v));
}
__device__ __forceinline__ void mma_bf16(float* d, const uint4& a, uint32_t b0, uint32_t b1) {
    asm volatile(
        "mma.sync.aligned.m16n8k16.row.col.f32.bf16.bf16.f32 "
        "{%0,%1,%2,%3},{%4,%5,%6,%7},{%8,%9},{%0,%1,%2,%3};\n"
        : "+f"(d[0]), "+f"(d[1]), "+f"(d[2]), "+f"(d[3])
        : "r"(a.x), "r"(a.y), "r"(a.z), "r"(a.w), "r"(b0), "r"(b1));
}
// pack one (row, col-pair) value pair into A-fragment layout (hi + lo planes)
__device__ __forceinline__ void pack_pair(uint32_t* dst, int row, int c0, float v0, float v1) {
    int ks = c0 >> 4, hcol = (c0 >> 3) & 1, g = (c0 >> 1) & 3;
    int lane = (row & 7) * 4 + g;
    int reg = hcol * 2 + ((row >> 3) & 1);
    int m = row >> 4;
    float h0 = bf_hi(v0), h1 = bf_hi(v1);
    dst[((ks * 2 + m) * 32 + lane) * 4 + reg]        = pk_bf2(h0, h1);
    dst[(((32 + ks) * 2 + m) * 32 + lane) * 4 + reg] = pk_bf2(v0 - h0, v1 - h1);
}

// ---------------- init: pack x_emb, h_prev into fragment buffers ----------------
__global__ void k_init(const int* __restrict__ x, const float* __restrict__ h_prev,
                       const float* __restrict__ emb) {
    int b = blockIdx.x, tid = threadIdx.x;   // 128 threads, 4 cols each
    const float* er = emb + (long)x[b] * HH;
    const float* hr = h_prev + b * HH;
    int c = tid * 4;
    float e0 = er[c], e1 = er[c + 1], e2 = er[c + 2], e3 = er[c + 3];
    float h0 = hr[c], h1 = hr[c + 1], h2 = hr[c + 2], h3 = hr[c + 3];
    pack_pair((uint32_t*)g_XF, b, c, e0, e1);
    pack_pair((uint32_t*)g_XF, b, c + 2, e2, e3);
    pack_pair((uint32_t*)g_H0F[0], b, c, h0, h1);
    pack_pair((uint32_t*)g_H0F[0], b, c + 2, h2, h3);
    pack_pair((uint32_t*)g_AF[0], b, c, h0, h1);
    pack_pair((uint32_t*)g_AF[0], b, c + 2, h2, h3);
}

__global__ void k_pack_c1(const float* __restrict__ c1) {
    int i = blockIdx.x * blockDim.x + threadIdx.x;
    if (i < VPAD) g_c1p[i] = (i < VOCAB) ? c1[i] : -1e30f;
}

// ---------------- pack V1 into bf16-split fragment layout (one-time) ----------------
__global__ void k_pack_b(const float* __restrict__ V1) {
    __shared__ float sv[16][257];
    int bx = blockIdx.x, ks = blockIdx.y, tid = threadIdx.x;
    int cbase = bx * 256;
    #pragma unroll
    for (int r = 0; r < 16; r++) {
        int col = cbase + tid;
        int k = ks * 16 + r;
        sv[r][tid] = (col < VOCAB) ? V1[(long)k * VOCAB + col] : 0.0f;
    }
    __syncthreads();
    for (int e = tid; e < 1024; e += 256) {
        int lane = e & 31, n8l = e >> 5;
        int colL = n8l * 8 + (lane >> 2);
        int rr = (lane & 3) * 2;
        float v0 = sv[rr][colL],     v1 = sv[rr + 1][colL];
        float v8 = sv[rr + 8][colL], v9 = sv[rr + 9][colL];
        float h0 = bf_hi(v0), h1 = bf_hi(v1), h8 = bf_hi(v8), h9 = bf_hi(v9);
        uint4 o;
        o.x = pk_bf2(h0, h1);
        o.y = pk_bf2(h8, h9);
        o.z = pk_bf2(v0 - h0, v1 - h1);
        o.w = pk_bf2(v8 - h8, v9 - h9);
        g_Bf[((long)ks * NB8 + bx * 32 + n8l) * 32 + lane] = o;
    }
}

// ---------------- pack the 5 small weight matrices (one-time) ----------------
__global__ void k_pack_w(const float* __restrict__ U0, const float* __restrict__ W0,
                         const float* __restrict__ V0, const float* __restrict__ U1,
                         const float* __restrict__ W1) {
    const float* src;
    int mat = blockIdx.z;
    switch (mat) {
        case 0: src = U0; break;
        case 1: src = W0; break;
        case 2: src = V0; break;
        case 3: src = U1; break;
        default: src = W1; break;
    }
    __shared__ float sv[16][257];
    int bx = blockIdx.x, ks = blockIdx.y, tid = threadIdx.x;
    int cbase = bx * 256;
    #pragma unroll
    for (int r = 0; r < 16; r++)
        sv[r][tid] = src[(long)(ks * 16 + r) * 512 + cbase + tid];
    __syncthreads();
    for (int e = tid; e < 1024; e += 256) {
        int lane = e & 31, n8l = e >> 5;
        int colL = n8l * 8 + (lane >> 2);
        int rr = (lane & 3) * 2;
        float v0 = sv[rr][colL],     v1 = sv[rr + 1][colL];
        float v8 = sv[rr + 8][colL], v9 = sv[rr + 9][colL];
        float h0 = bf_hi(v0), h1 = bf_hi(v1), h8 = bf_hi(v8), h9 = bf_hi(v9);
        uint4 o;
        o.x = pk_bf2(h0, h1);
        o.y = pk_bf2(h8, h9);
        o.z = pk_bf2(v0 - h0, v1 - h1);
        o.w = pk_bf2(v8 - h8, v9 - h9);
        g_WF[(long)mat * 65536 + ((long)ks * 64 + bx * 32 + n8l) * 32 + lane] = o;
    }
}

// ---------------- mma core for 32x512x512 (split-bf16, 3 acc chains) ----------------
template<bool DUAL>
__device__ __forceinline__ void smma_core(
        const uint4* __restrict__ A1f, const uint4* __restrict__ A2f,
        const uint4* __restrict__ W1f, const uint4* __restrict__ W2f,
        int n8g, int lane, float acc[3][2][4]) {
    #pragma unroll 2
    for (int ks = 0; ks < 32; ks++) {
        uint4 a1h0 = A1f[(ks * 2 + 0) * 32 + lane];
        uint4 a1h1 = A1f[(ks * 2 + 1) * 32 + lane];
        uint4 a1l0 = A1f[((32 + ks) * 2 + 0) * 32 + lane];
        uint4 a1l1 = A1f[((32 + ks) * 2 + 1) * 32 + lane];
        uint4 w1 = W1f[(ks * 64 + n8g) * 32 + lane];
        mma_bf16(acc[0][0], a1h0, w1.x, w1.y);
        mma_bf16(acc[0][1], a1h1, w1.x, w1.y);
        mma_bf16(acc[1][0], a1l0, w1.x, w1.y);
        mma_bf16(acc[1][1], a1l1, w1.x, w1.y);
        mma_bf16(acc[2][0], a1h0, w1.z, w1.w);
        mma_bf16(acc[2][1], a1h1, w1.z, w1.w);
        if (DUAL) {
            uint4 a2h0 = A2f[(ks * 2 + 0) * 32 + lane];
            uint4 a2h1 = A2f[(ks * 2 + 1) * 32 + lane];
            uint4 a2l0 = A2f[((32 + ks) * 2 + 0) * 32 + lane];
            uint4 a2l1 = A2f[((32 + ks) * 2 + 1) * 32 + lane];
            uint4 w2 = W2f[(ks * 64 + n8g) * 32 + lane];
            mma_bf16(acc[0][0], a2h0, w2.x, w2.y);
            mma_bf16(acc[0][1], a2h1, w2.x, w2.y);
            mma_bf16(acc[1][0], a2l0, w2.x, w2.y);
            mma_bf16(acc[1][1], a2l1, w2.x, w2.y);
            mma_bf16(acc[2][0], a2h0, w2.z, w2.w);
            mma_bf16(acc[2][1], a2h1, w2.z, w2.w);
        }
    }
}

// ---------------- RNN cell: tanh(A1@W1 + A2@W2 + bias) -> fragment output ----------------
// grid 32 x 64 threads (2 warps, 1 n8 per warp)
template<bool WRITE_OUTH>
__global__ void __launch_bounds__(64) k_cell(
        const uint4* __restrict__ A1f, const uint4* __restrict__ A2f,
        const uint4* __restrict__ W1f, const uint4* __restrict__ W2f,
        const float* __restrict__ bias, uint32_t* __restrict__ dstF,
        float* __restrict__ out_h, int t, int T) {
    int tid = threadIdx.x, lane = tid & 31;
    int n8g = blockIdx.x * 2 + (tid >> 5);
    float acc[3][2][4] = {};
    smma_core<true>(A1f, A2f, W1f, W2f, n8g, lane, acc);

    int c0 = n8g * 8 + (lane & 3) * 2;
    float b0v = bias[c0], b1v = bias[c0 + 1];
    int ks = n8g >> 1, hcol = n8g & 1, g = lane & 3;
    int lane_t = (lane >> 2) * 4 + g;
    #pragma unroll
    for (int m = 0; m < 2; m++) {
        #pragma unroll
        for (int rb = 0; rb < 2; rb++) {
            float v0 = tanhf(acc[0][m][rb * 2] + acc[1][m][rb * 2] + acc[2][m][rb * 2] + b0v);
            float v1 = tanhf(acc[0][m][rb * 2 + 1] + acc[1][m][rb * 2 + 1] + acc[2][m][rb * 2 + 1] + b1v);
            int reg = hcol * 2 + rb;
            float h0 = bf_hi(v0), h1 = bf_hi(v1);
            dstF[((ks * 2 + m) * 32 + lane_t) * 4 + reg]        = pk_bf2(h0, h1);
            dstF[(((32 + ks) * 2 + m) * 32 + lane_t) * 4 + reg] = pk_bf2(v0 - h0, v1 - h1);
            if (WRITE_OUTH) {
                int row = m * 16 + (lane >> 2) + rb * 8;
                *(float2*)&out_h[((long)row * T + t) * 512 + c0] = make_float2(v0, v1);
            }
        }
    }
}

// ---------------- layer-0 head: exp(h0@V0 + c0) + row partial sums ----------------
__global__ void __launch_bounds__(64) k_head0(
        const uint4* __restrict__ A1f, const uint4* __restrict__ Wf,
        const float* __restrict__ bias) {
    int tid = threadIdx.x, lane = tid & 31;
    int n8g = blockIdx.x * 2 + (tid >> 5);
    float acc[3][2][4] = {};
    smma_core<false>(A1f, nullptr, Wf, nullptr, n8g, lane, acc);

    int c0 = n8g * 8 + (lane & 3) * 2;
    float b0v = bias[c0], b1v = bias[c0 + 1];
    #pragma unroll
    for (int m = 0; m < 2; m++) {
        #pragma unroll
        for (int rb = 0; rb < 2; rb++) {
            float l0 = acc[0][m][rb * 2] + acc[1][m][rb * 2] + acc[2][m][rb * 2] + b0v;
            float l1 = acc[0][m][rb * 2 + 1] + acc[1][m][rb * 2 + 1] + acc[2][m][rb * 2 + 1] + b1v;
            float e0 = __expf(l0), e1 = __expf(l1);   // shift-free: |logits0| small
            int row = m * 16 + (lane >> 2) + rb * 8;
            *(float2*)&g_e0[row * 512 + c0] = make_float2(e0, e1);
            float s = e0 + e1;
            s += __shfl_xor_sync(0xffffffffu, s, 1);
            s += __shfl_xor_sync(0xffffffffu, s, 2);
            if ((lane & 3) == 0) g_ps0[row * 64 + n8g] = s;
        }
    }
}

// ---------------- x1 = tanh(e/S), packed to fragments ----------------
__global__ void __launch_bounds__(128) k_fix() {
    __shared__ float sr[64];
    __shared__ float sS;
    int b = blockIdx.x, tid = threadIdx.x;
    if (tid < 64) sr[tid] = g_ps0[b * 64 + tid];
    __syncthreads();
    if (tid < 32) {
        float v = sr[tid] + sr[tid + 32];
        #pragma unroll
        for (int off = 16; off > 0; off >>= 1)
            v += __shfl_xor_sync(0xffffffffu, v, off);
        if (tid == 0) sS = v;
    }
    __syncthreads();
    float inv = 1.0f / sS;
    int c = tid * 4;
    float4 e = *(const float4*)&g_e0[b * 512 + c];
    float v0 = tanhf(e.x * inv), v1 = tanhf(e.y * inv);
    float v2 = tanhf(e.z * inv), v3 = tanhf(e.w * inv);
    pack_pair((uint32_t*)g_X1F, b, c, v0, v1);
    pack_pair((uint32_t*)g_X1F, b, c + 2, v2, v3);
}

// ---------------- big GEMM: 32 x VPAD via bf16-split mma + exp epilogue ----------------
__global__ void __launch_bounds__(256) k_big(const uint4* __restrict__ Af) {
    int tid = threadIdx.x, w = tid >> 5, lane = tid & 31;
    int bx = blockIdx.x;
    int n8base = bx * 32 + w * 4;
    float acc[2][4][4];
    #pragma unroll
    for (int m = 0; m < 2; m++)
        #pragma unroll
        for (int n = 0; n < 4; n++)
            #pragma unroll
            for (int rr = 0; rr < 4; rr++) acc[m][n][rr] = 0.f;

    #pragma unroll 2
    for (int ks = 0; ks < 32; ks++) {
        uint4 ah0 = Af[(ks * 2 + 0) * 32 + lane];
        uint4 ah1 = Af[(ks * 2 + 1) * 32 + lane];
        uint4 al0 = Af[((32 + ks) * 2 + 0) * 32 + lane];
        uint4 al1 = Af[((32 + ks) * 2 + 1) * 32 + lane];
        uint4 bv[4];
        #pragma unroll
        for (int n = 0; n < 4; n++)
            bv[n] = g_Bf[((long)ks * NB8 + n8base + n) * 32 + lane];
        #pragma unroll
        for (int n = 0; n < 4; n++) {
            mma_bf16(acc[0][n], ah0, bv[n].x, bv[n].y);
            mma_bf16(acc[1][n], ah1, bv[n].x, bv[n].y);
            mma_bf16(acc[0][n], al0, bv[n].x, bv[n].y);
            mma_bf16(acc[1][n], al1, bv[n].x, bv[n].y);
            mma_bf16(acc[0][n], ah0, bv[n].z, bv[n].w);
            mma_bf16(acc[1][n], ah1, bv[n].z, bv[n].w);
        }
    }

    __shared__ float s_sum[8][32];
    __shared__ float s_max[8][32];
    __shared__ int   s_idx[8][32];
    int colw = bx * 256 + w * 32;
    float rsum[4] = {0.f, 0.f, 0.f, 0.f};
    float rmax[4] = {-3e38f, -3e38f, -3e38f, -3e38f};
    int   ridx[4] = {0, 0, 0, 0};

    #pragma unroll
    for (int m = 0; m < 2; m++) {
        #pragma unroll
        for (int n = 0; n < 4; n++) {
            int c0 = colw + n * 8 + ((lane & 3) << 1);
            float bias0 = g_c1p[c0], bias1 = g_c1p[c0 + 1];
            {
                float l0 = acc[m][n][0] + bias0, l1 = acc[m][n][1] + bias1;
                float e0 = __expf(l0), e1 = __expf(l1);
                int row = m * 16 + (lane >> 2);
                *(float2*)&g_E[(long)row * VPAD + c0] = make_float2(e0, e1);
                int slot = m * 2;
                rsum[slot] += e0 + e1;
                if (l0 > rmax[slot] || (l0 == rmax[slot] && c0 < ridx[slot])) { rmax[slot] = l0; ridx[slot] = c0; }
                if (l1 > rmax[slot] || (l1 == rmax[slot] && c0 + 1 < ridx[slot])) { rmax[slot] = l1; ridx[slot] = c0 + 1; }
            }
            {
                float l0 = acc[m][n][2] + bias0, l1 = acc[m][n][3] + bias1;
                float e0 = __expf(l0), e1 = __expf(l1);
                int row = m * 16 + (lane >> 2) + 8;
                *(float2*)&g_E[(long)row * VPAD + c0] = make_float2(e0, e1);
                int slot = m * 2 + 1;
                rsum[slot] += e0 + e1;
                if (l0 > rmax[slot] || (l0 == rmax[slot] && c0 < ridx[slot])) { rmax[slot] = l0; ridx[slot] = c0; }
                if (l1 > rmax[slot] || (l1 == rmax[slot] && c0 + 1 < ridx[slot])) { rmax[slot] = l1; ridx[slot] = c0 + 1; }
            }
        }
    }
    #pragma unroll
    for (int off = 1; off <= 2; off <<= 1) {
        #pragma unroll
        for (int slot = 0; slot < 4; slot++) {
            rsum[slot] += __shfl_xor_sync(0xffffffffu, rsum[slot], off);
            float v = __shfl_xor_sync(0xffffffffu, rmax[slot], off);
            int   i = __shfl_xor_sync(0xffffffffu, ridx[slot], off);
            if (v > rmax[slot] || (v == rmax[slot] && i < ridx[slot])) { rmax[slot] = v; ridx[slot] = i; }
        }
    }
    if ((lane & 3) == 0) {
        #pragma unroll
        for (int slot = 0; slot < 4; slot++) {
            int row = (slot >> 1) * 16 + (lane >> 2) + (slot & 1) * 8;
            s_sum[w][row] = rsum[slot];
            s_max[w][row] = rmax[slot];
            s_idx[w][row] = ridx[slot];
        }
    }
    __syncthreads();
    if (tid < 32) {
        int row = tid;
        float ps = 0.f, pv = -3e38f; int pi = 0;
        #pragma unroll
        for (int ww = 0; ww < 8; ww++) {
            ps += s_sum[ww][row];
            float v = s_max[ww][row]; int i = s_idx[ww][row];
            if (v > pv || (v == pv && i < pi)) { pv = v; pi = i; }
        }
        g_psum[row * NBP + bx] = ps;
        g_pmax[row * NBP + bx] = pv;
        g_pidx[row * NBP + bx] = pi;
    }
}

// ---------------- combine: invS + argmax + feedback embed (packed to frags) ----------------
__global__ void __launch_bounds__(128) k_comb(const float* __restrict__ emb) {
    __shared__ float rs[128], rv[128];
    __shared__ int   ri[128];
    int row = blockIdx.x, tid = threadIdx.x;
    float s = 0.f, mv = -3e38f; int mi = 0;
    for (int i = tid; i < NBLK; i += 128) {
        s += g_psum[row * NBP + i];
        float v = g_pmax[row * NBP + i]; int ix = g_pidx[row * NBP + i];
        if (v > mv || (v == mv && ix < mi)) { mv = v; mi = ix; }
    }
    rs[tid] = s; rv[tid] = mv; ri[tid] = mi;
    __syncthreads();
    for (int st = 64; st > 0; st >>= 1) {
        if (tid < st) {
            rs[tid] += rs[tid + st];
            float v = rv[tid + st]; int i = ri[tid + st];
            if (v > rv[tid] || (v == rv[tid] && i < ri[tid])) { rv[tid] = v; ri[tid] = i; }
        }
        __syncthreads();
    }
    if (tid == 0) g_invS[row] = 1.0f / rs[0];
    int am = ri[0];
    const float* er = emb + (long)am * HH;
    int c = tid * 4;
    float v0 = er[c], v1 = er[c + 1], v2 = er[c + 2], v3 = er[c + 3];
    pack_pair((uint32_t*)g_XF, row, c, v0, v1);
    pack_pair((uint32_t*)g_XF, row, c + 2, v2, v3);
}

// ---------------- write y ----------------
__global__ void k_writey(float* __restrict__ out_y, int t, int T) {
    int b = blockIdx.y;
    float inv = g_invS[b];
    const float* erow = &g_E[(long)b * VPAD];
    float* yrow = &out_y[((long)b * T + t) * VOCAB];
    for (int j = blockIdx.x * blockDim.x + threadIdx.x; j < VOCAB; j += gridDim.x * blockDim.x)
        yrow[j] = erow[j] * inv;
}

// ---------------- host launcher ----------------
extern "C" void kernel_launch(void* const* d_in, const int* in_sizes, int n_in,
                              void* d_out, int out_size) {
    const int*   x      = (const int*)d_in[0];
    const float* h_prev = (const float*)d_in[3];
    const float* emb    = (const float*)d_in[4];
    const float* U0     = (const float*)d_in[5];
    const float* W0     = (const float*)d_in[6];
    const float* b0     = (const float*)d_in[7];
    const float* V0     = (const float*)d_in[8];
    const float* c0     = (const float*)d_in[9];
    const float* U1     = (const float*)d_in[10];
    const float* W1     = (const float*)d_in[11];
    const float* b1     = (const float*)d_in[12];
    const float* V1     = (const float*)d_in[13];
    const float* c1     = (const float*)d_in[14];

    float* out = (float*)d_out;
    int T = out_size / (BB * (HH + VOCAB));
    float* out_h = out;
    float* out_y = out + (long)BB * T * HH;

    uint4 *p_XF, *p_H0F, *p_AF, *p_X1F, *p_WF;
    cudaGetSymbolAddress((void**)&p_XF,  g_XF);
    cudaGetSymbolAddress((void**)&p_H0F, g_H0F);
    cudaGetSymbolAddress((void**)&p_AF,  g_AF);
    cudaGetSymbolAddress((void**)&p_X1F, g_X1F);
    cudaGetSymbolAddress((void**)&p_WF,  g_WF);
    const int FRAG = 2 * 32 * 2 * 32;          // uint4 elements per frag buffer
    const uint4* U0f = p_WF + 0L * 65536;
    const uint4* W0f = p_WF + 1L * 65536;
    const uint4* V0f = p_WF + 2L * 65536;
    const uint4* U1f = p_WF + 3L * 65536;
    const uint4* W1f = p_WF + 4L * 65536;

    k_init<<<BB, 128>>>(x, h_prev, emb);
    k_pack_c1<<<(VPAD + 255) / 256, 256>>>(c1);
    k_pack_w<<<dim3(2, 32, 5), 256>>>(U0, W0, V0, U1, W1);
    k_pack_b<<<dim3(197, 32), 256>>>(V1);

    for (int t = 0; t < T; t++) {
        int cur = t & 1, nxt = cur ^ 1;
        // h0 = tanh(x@U0 + h0p@W0 + b0)
        k_cell<false><<<32, 64>>>(p_XF, p_H0F + cur * FRAG, U0f, W0f, b0,
                                  (uint32_t*)(p_H0F + nxt * FRAG), nullptr, 0, T);
        // e0 = exp(h0@V0 + c0), row partials
        k_head0<<<32, 64>>>(p_H0F + nxt * FRAG, V0f, c0);
        // x1 = tanh(e0/S) -> frags
        k_fix<<<BB, 128>>>();
        // h1 = tanh(x1@U1 + h1p@W1 + b1) -> frags + out_h
        k_cell<true><<<32, 64>>>(p_X1F, p_AF + cur * FRAG, U1f, W1f, b1,
                                 (uint32_t*)(p_AF + nxt * FRAG), out_h, t, T);
        // logits1 -> exp + partials
        k_big<<<NBLK, 256>>>(p_AF + nxt * FRAG);
        // invS + argmax + feedback embed
        k_comb<<<BB, 128>>>(emb);
        // y out
        k_writey<<<dim3(64, BB), 256>>>(out_y, t, T);
    }
}

// round 8
// speedup vs baseline: 1.8656x; 1.8656x over previous
#include <cuda_runtime.h>
#include <cuda_bf16.h>
#include <math.h>
#include <stdint.h>

#define BB 32
#define HH 512
#define VOCAB 50257
#define VPAD  50432          // multiple of 256
#define NB8   (VPAD/8)       // 6304 fragment columns
#define NBLK  (VPAD/256)     // 197 big-gemm blocks (256 cols each)
#define NBP   208            // padded partial stride

// ---------------- device scratch ----------------
__device__ float g_xcur[BB * HH];
__device__ float g_h0s[2][BB * HH];
__device__ float g_h1s[2][BB * HH];
__device__ float g_e0[BB * HH];                // exp(logits0)
__device__ float g_ps0[BB * 128];              // layer-0 partial row sums per block
__device__ float g_x1[BB * HH];
__device__ uint4 g_Af[2 * 32 * 2 * 32];        // [hl][ks][m][lane] A fragments for k_big
__device__ uint4 g_Bf[(long)32 * NB8 * 32];    // [ks][n8][lane] -> {bh0,bh1,bl0,bl1} (103MB)
__device__ float g_c1p[VPAD];
__device__ float g_E[BB * VPAD];               // exp(logits1)
__device__ float g_psum[BB * NBP];
__device__ float g_pmax[BB * NBP];
__device__ int   g_pidx[BB * NBP];
__device__ float g_invS[BB];

// ---------------- helpers ----------------
__device__ __forceinline__ uint32_t pk_bf2(float a, float b) {
    uint32_t ua = (uint32_t)__bfloat16_as_ushort(__float2bfloat16_rn(a));
    uint32_t ub = (uint32_t)__bfloat16_as_ushort(__float2bfloat16_rn(b));
    return ua | (ub << 16);
}
__device__ __forceinline__ float bf_hi(float v) {
    return __bfloat162float(__float2bfloat16_rn(v));
}
__device__ __forceinline__ void mma_bf16(float* d, const uint4& a, uint32_t b0, uint32_t b1) {
    asm volatile(
        "mma.sync.aligned.m16n8k16.row.col.f32.bf16.bf16.f32 "
        "{%0,%1,%2,%3},{%4,%5,%6,%7},{%8,%9},{%0,%1,%2,%3};\n"
        : "+f"(d[0]), "+f"(d[1]), "+f"(d[2]), "+f"(d[3])
        : "r"(a.x), "r"(a.y), "r"(a.z), "r"(a.w), "r"(b0), "r"(b1));
}

// ---------------- init ----------------
__global__ void k_init(const int* __restrict__ x, const float* __restrict__ h_prev,
                       const float* __restrict__ emb) {
    int b = blockIdx.x, j = threadIdx.x;
    g_xcur[b * HH + j]   = emb[(long)x[b] * HH + j];
    g_h0s[0][b * HH + j] = h_prev[b * HH + j];
    g_h1s[0][b * HH + j] = h_prev[b * HH + j];
}

__global__ void k_pack_c1(const float* __restrict__ c1) {
    int i = blockIdx.x * blockDim.x + threadIdx.x;
    if (i < VPAD) g_c1p[i] = (i < VOCAB) ? c1[i] : -1e30f;
}

// ---------------- pack V1 into bf16-split mma fragment layout (one-time) ----------------
__global__ void k_pack_b(const float* __restrict__ V1) {
    __shared__ float sv[16][257];
    int bx = blockIdx.x, ks = blockIdx.y, tid = threadIdx.x;
    int cbase = bx * 256;
    #pragma unroll
    for (int r = 0; r < 16; r++) {
        int col = cbase + tid;
        int k = ks * 16 + r;
        sv[r][tid] = (col < VOCAB) ? V1[(long)k * VOCAB + col] : 0.0f;
    }
    __syncthreads();
    for (int e = tid; e < 1024; e += 256) {
        int lane = e & 31, n8l = e >> 5;
        int colL = n8l * 8 + (lane >> 2);
        int rr = (lane & 3) * 2;
        float v0 = sv[rr][colL],     v1 = sv[rr + 1][colL];
        float v8 = sv[rr + 8][colL], v9 = sv[rr + 9][colL];
        float h0 = bf_hi(v0), h1 = bf_hi(v1), h8 = bf_hi(v8), h9 = bf_hi(v9);
        uint4 o;
        o.x = pk_bf2(h0, h1);
        o.y = pk_bf2(h8, h9);
        o.z = pk_bf2(v0 - h0, v1 - h1);
        o.w = pk_bf2(v8 - h8, v9 - h9);
        g_Bf[((long)ks * NB8 + bx * 32 + n8l) * 32 + lane] = o;
    }
}

// ---------------- small GEMM: full-staging, 256 threads, 2-way split-K ----------------
// MODE 0: cell0  out = tanh(A1@W1 + A2@W2 + b)
// MODE 1: head0  e0 = exp(A1@W1 + b), partial row sums -> g_ps0
// MODE 2: cell1  out = tanh(A1@W1 + A2@W2 + b)  + out_h + A-fragment pack
template<int MODE>
__global__ void __launch_bounds__(256) k_cellx(
        const float* __restrict__ A1, const float* __restrict__ A2,
        const float* __restrict__ W1, const float* __restrict__ W2,
        const float* __restrict__ bias, float* __restrict__ outp,
        float* __restrict__ out_h, int t, int T) {
    constexpr bool DUAL = (MODE != 1);
    extern __shared__ float sm[];
    float* sA1 = sm;                                   // 32 x 516
    float* sA2 = DUAL ? (sm + 16512) : nullptr;        // 32 x 516
    float* sW1 = sm + (DUAL ? 33024 : 16512);          // 4 x 516
    float* sW2 = DUAL ? (sW1 + 2064) : nullptr;        // 4 x 516
    float* sRed = sW1 + (DUAL ? 4128 : 2064);          // 256
    float* sH  = sRed + 256;                           // 32 x 5 (MODE 2)

    int tid = threadIdx.x;
    int jb = blockIdx.x * 4;
    int half = tid >> 7;        // K-half
    int sub  = tid & 127;
    int jl = sub & 3, r = sub >> 2;

    // ---- stage everything (one deep-MLP phase) ----
    const float4* gA1 = (const float4*)A1;
    #pragma unroll
    for (int i = 0; i < 16; i++) {
        int q = tid + i * 256;                 // 0..4095 float4
        int rr = q >> 7, cc = q & 127;
        ((float4*)(sA1 + rr * 516))[cc] = gA1[q];
    }
    if (DUAL) {
        const float4* gA2 = (const float4*)A2;
        #pragma unroll
        for (int i = 0; i < 16; i++) {
            int q = tid + i * 256;
            int rr = q >> 7, cc = q & 127;
            ((float4*)(sA2 + rr * 516))[cc] = gA2[q];
        }
    }
    #pragma unroll
    for (int i = 0; i < 8; i++) {
        int q = tid + i * 256;                 // 0..2047
        int kk = q >> 2, jj = q & 3;
        sW1[jj * 516 + kk] = W1[kk * 512 + jb + jj];
        if (DUAL) sW2[jj * 516 + kk] = W2[kk * 512 + jb + jj];
    }
    __syncthreads();

    // ---- compute: K half of 256 per thread, 4 accumulators ----
    float ac0 = 0.f, ac1 = 0.f, ac2 = 0.f, ac3 = 0.f;
    {
        const float4* a1 = (const float4*)(sA1 + r * 516) + half * 64;
        const float4* w1 = (const float4*)(sW1 + jl * 516) + half * 64;
        #pragma unroll
        for (int k = 0; k < 64; k += 4) {
            float4 x0 = a1[k],     y0 = w1[k];
            float4 x1v = a1[k + 1], y1 = w1[k + 1];
            float4 x2 = a1[k + 2], y2 = w1[k + 2];
            float4 x3 = a1[k + 3], y3 = w1[k + 3];
            ac0 = fmaf(x0.x, y0.x, ac0); ac0 = fmaf(x0.y, y0.y, ac0);
            ac0 = fmaf(x0.z, y0.z, ac0); ac0 = fmaf(x0.w, y0.w, ac0);
            ac1 = fmaf(x1v.x, y1.x, ac1); ac1 = fmaf(x1v.y, y1.y, ac1);
            ac1 = fmaf(x1v.z, y1.z, ac1); ac1 = fmaf(x1v.w, y1.w, ac1);
            ac2 = fmaf(x2.x, y2.x, ac2); ac2 = fmaf(x2.y, y2.y, ac2);
            ac2 = fmaf(x2.z, y2.z, ac2); ac2 = fmaf(x2.w, y2.w, ac2);
            ac3 = fmaf(x3.x, y3.x, ac3); ac3 = fmaf(x3.y, y3.y, ac3);
            ac3 = fmaf(x3.z, y3.z, ac3); ac3 = fmaf(x3.w, y3.w, ac3);
        }
    }
    if (DUAL) {
        const float4* a2 = (const float4*)(sA2 + r * 516) + half * 64;
        const float4* w2 = (const float4*)(sW2 + jl * 516) + half * 64;
        #pragma unroll
        for (int k = 0; k < 64; k += 4) {
            float4 x0 = a2[k],     y0 = w2[k];
            float4 x1v = a2[k + 1], y1 = w2[k + 1];
            float4 x2 = a2[k + 2], y2 = w2[k + 2];
            float4 x3 = a2[k + 3], y3 = w2[k + 3];
            ac0 = fmaf(x0.x, y0.x, ac0); ac0 = fmaf(x0.y, y0.y, ac0);
            ac0 = fmaf(x0.z, y0.z, ac0); ac0 = fmaf(x0.w, y0.w, ac0);
            ac1 = fmaf(x1v.x, y1.x, ac1); ac1 = fmaf(x1v.y, y1.y, ac1);
            ac1 = fmaf(x1v.z, y1.z, ac1); ac1 = fmaf(x1v.w, y1.w, ac1);
            ac2 = fmaf(x2.x, y2.x, ac2); ac2 = fmaf(x2.y, y2.y, ac2);
            ac2 = fmaf(x2.z, y2.z, ac2); ac2 = fmaf(x2.w, y2.w, ac2);
            ac3 = fmaf(x3.x, y3.x, ac3); ac3 = fmaf(x3.y, y3.y, ac3);
            ac3 = fmaf(x3.z, y3.z, ac3); ac3 = fmaf(x3.w, y3.w, ac3);
        }
    }
    sRed[half * 128 + sub] = (ac0 + ac1) + (ac2 + ac3);
    __syncthreads();

    // ---- epilogue (first 128 threads hold outputs) ----
    float o = 0.f;
    if (tid < 128) {
        o = sRed[tid] + sRed[128 + tid] + bias[jb + jl];
        if (MODE == 0) {
            o = tanhf(o);
            outp[r * 512 + jb + jl] = o;
        } else if (MODE == 1) {
            float e = __expf(o);                 // |logits0| small: shift-free is safe
            g_e0[r * 512 + jb + jl] = e;
            float v = e;
            v += __shfl_down_sync(0xffffffffu, v, 2);
            v += __shfl_down_sync(0xffffffffu, v, 1);
            if ((tid & 3) == 0) g_ps0[r * 128 + blockIdx.x] = v;
        } else {
            o = tanhf(o);
            outp[r * 512 + jb + jl] = o;
            out_h[((long)r * T + t) * 512 + jb + jl] = o;
            sH[r * 5 + jl] = o;
        }
    }
    if (MODE == 2) {
        __syncthreads();
        if (tid < 128) {
            // write the 128 A-fragment words this block owns (hi + lo planes)
            int hl = tid >> 6, rem = tid & 63;
            int ps = rem & 1, rr = rem >> 1;
            int c0i = jb + ps * 2;
            float v0 = sH[rr * 5 + ps * 2], v1 = sH[rr * 5 + ps * 2 + 1];
            float h0f = bf_hi(v0), h1f = bf_hi(v1);
            uint32_t pk = hl ? pk_bf2(v0 - h0f, v1 - h1f) : pk_bf2(h0f, h1f);
            int ks = c0i >> 4, kk = c0i & 15;
            int hcol = (kk >> 3) & 1, g = (kk >> 1) & 3;
            int lane = (rr & 7) * 4 + g;
            int reg = hcol * 2 + ((rr >> 3) & 1);
            int mtile = rr >> 4;
            ((uint32_t*)g_Af)[(((hl * 32 + ks) * 2 + mtile) * 32 + lane) * 4 + reg] = pk;
        }
    }
}

// ---------------- x1 = tanh(softmax(logits0)) from e0 + partial sums ----------------
__global__ void __launch_bounds__(256) k_sfm(float* __restrict__ x1) {
    __shared__ float sp[128];
    __shared__ float sInv;
    int b = blockIdx.x, tid = threadIdx.x;
    if (tid < 128) sp[tid] = g_ps0[b * 128 + tid];
    __syncthreads();
    if (tid < 32) {
        float v = sp[tid] + sp[tid + 32] + sp[tid + 64] + sp[tid + 96];
        #pragma unroll
        for (int off = 16; off > 0; off >>= 1)
            v += __shfl_xor_sync(0xffffffffu, v, off);
        if (tid == 0) sInv = 1.0f / v;
    }
    __syncthreads();
    float inv = sInv;
    x1[b * 512 + tid]       = tanhf(g_e0[b * 512 + tid] * inv);
    x1[b * 512 + tid + 256] = tanhf(g_e0[b * 512 + tid + 256] * inv);
}

// ---------------- big GEMM: 32 x VPAD via bf16-split mma + exp epilogue ----------------
__global__ void __launch_bounds__(256) k_big() {
    int tid = threadIdx.x, w = tid >> 5, lane = tid & 31;
    int bx = blockIdx.x;
    int n8base = bx * 32 + w * 4;
    float acc[2][4][4];
    #pragma unroll
    for (int m = 0; m < 2; m++)
        #pragma unroll
        for (int n = 0; n < 4; n++)
            #pragma unroll
            for (int rr = 0; rr < 4; rr++) acc[m][n][rr] = 0.f;

    #pragma unroll 2
    for (int ks = 0; ks < 32; ks++) {
        uint4 ah0 = g_Af[(ks * 2 + 0) * 32 + lane];
        uint4 ah1 = g_Af[(ks * 2 + 1) * 32 + lane];
        uint4 al0 = g_Af[((32 + ks) * 2 + 0) * 32 + lane];
        uint4 al1 = g_Af[((32 + ks) * 2 + 1) * 32 + lane];
        uint4 bv[4];
        #pragma unroll
        for (int n = 0; n < 4; n++)
            bv[n] = g_Bf[((long)ks * NB8 + n8base + n) * 32 + lane];
        #pragma unroll
        for (int n = 0; n < 4; n++) {
            mma_bf16(acc[0][n], ah0, bv[n].x, bv[n].y);
            mma_bf16(acc[1][n], ah1, bv[n].x, bv[n].y);
            mma_bf16(acc[0][n], al0, bv[n].x, bv[n].y);
            mma_bf16(acc[1][n], al1, bv[n].x, bv[n].y);
            mma_bf16(acc[0][n], ah0, bv[n].z, bv[n].w);
            mma_bf16(acc[1][n], ah1, bv[n].z, bv[n].w);
        }
    }

    __shared__ float s_sum[8][32];
    __shared__ float s_max[8][32];
    __shared__ int   s_idx[8][32];
    int colw = bx * 256 + w * 32;
    float rsum[4] = {0.f, 0.f, 0.f, 0.f};
    float rmax[4] = {-3e38f, -3e38f, -3e38f, -3e38f};
    int   ridx[4] = {0, 0, 0, 0};

    #pragma unroll
    for (int m = 0; m < 2; m++) {
        #pragma unroll
        for (int n = 0; n < 4; n++) {
            int c0 = colw + n * 8 + ((lane & 3) << 1);
            float bias0 = g_c1p[c0], bias1 = g_c1p[c0 + 1];
            {
                float l0 = acc[m][n][0] + bias0, l1 = acc[m][n][1] + bias1;
                float e0 = __expf(l0), e1 = __expf(l1);
                int row = m * 16 + (lane >> 2);
                *(float2*)&g_E[(long)row * VPAD + c0] = make_float2(e0, e1);
                int slot = m * 2;
                rsum[slot] += e0 + e1;
                if (l0 > rmax[slot] || (l0 == rmax[slot] && c0 < ridx[slot])) { rmax[slot] = l0; ridx[slot] = c0; }
                if (l1 > rmax[slot] || (l1 == rmax[slot] && c0 + 1 < ridx[slot])) { rmax[slot] = l1; ridx[slot] = c0 + 1; }
            }
            {
                float l0 = acc[m][n][2] + bias0, l1 = acc[m][n][3] + bias1;
                float e0 = __expf(l0), e1 = __expf(l1);
                int row = m * 16 + (lane >> 2) + 8;
                *(float2*)&g_E[(long)row * VPAD + c0] = make_float2(e0, e1);
                int slot = m * 2 + 1;
                rsum[slot] += e0 + e1;
                if (l0 > rmax[slot] || (l0 == rmax[slot] && c0 < ridx[slot])) { rmax[slot] = l0; ridx[slot] = c0; }
                if (l1 > rmax[slot] || (l1 == rmax[slot] && c0 + 1 < ridx[slot])) { rmax[slot] = l1; ridx[slot] = c0 + 1; }
            }
        }
    }
    #pragma unroll
    for (int off = 1; off <= 2; off <<= 1) {
        #pragma unroll
        for (int slot = 0; slot < 4; slot++) {
            rsum[slot] += __shfl_xor_sync(0xffffffffu, rsum[slot], off);
            float v = __shfl_xor_sync(0xffffffffu, rmax[slot], off);
            int   i = __shfl_xor_sync(0xffffffffu, ridx[slot], off);
            if (v > rmax[slot] || (v == rmax[slot] && i < ridx[slot])) { rmax[slot] = v; ridx[slot] = i; }
        }
    }
    if ((lane & 3) == 0) {
        #pragma unroll
        for (int slot = 0; slot < 4; slot++) {
            int row = (slot >> 1) * 16 + (lane >> 2) + (slot & 1) * 8;
            s_sum[w][row] = rsum[slot];
            s_max[w][row] = rmax[slot];
            s_idx[w][row] = ridx[slot];
        }
    }
    __syncthreads();
    if (tid < 32) {
        int row = tid;
        float ps = 0.f, pv = -3e38f; int pi = 0;
        #pragma unroll
        for (int ww = 0; ww < 8; ww++) {
            ps += s_sum[ww][row];
            float v = s_max[ww][row]; int i = s_idx[ww][row];
            if (v > pv || (v == pv && i < pi)) { pv = v; pi = i; }
        }
        g_psum[row * NBP + bx] = ps;
        g_pmax[row * NBP + bx] = pv;
        g_pidx[row * NBP + bx] = pi;
    }
}

// ---------------- combine partials: invS + argmax + embed feedback ----------------
__global__ void __launch_bounds__(128) k_comb(const float* __restrict__ emb) {
    __shared__ float rs[128], rv[128];
    __shared__ int   ri[128];
    int row = blockIdx.x, tid = threadIdx.x;
    float s = 0.f, mv = -3e38f; int mi = 0;
    for (int i = tid; i < NBLK; i += 128) {
        s += g_psum[row * NBP + i];
        float v = g_pmax[row * NBP + i]; int ix = g_pidx[row * NBP + i];
        if (v > mv || (v == mv && ix < mi)) { mv = v; mi = ix; }
    }
    rs[tid] = s; rv[tid] = mv; ri[tid] = mi;
    __syncthreads();
    for (int st = 64; st > 0; st >>= 1) {
        if (tid < st) {
            rs[tid] += rs[tid + st];
            float v = rv[tid + st]; int i = ri[tid + st];
            if (v > rv[tid] || (v == rv[tid] && i < ri[tid])) { rv[tid] = v; ri[tid] = i; }
        }
        __syncthreads();
    }
    if (tid == 0) g_invS[row] = 1.0f / rs[0];
    int am = ri[0];
    for (int j = tid; j < 512; j += 128)
        g_xcur[row * 512 + j] = emb[(long)am * 512 + j];
}

// ---------------- write y ----------------
__global__ void k_writey(float* __restrict__ out_y, int t, int T) {
    int b = blockIdx.y;
    float inv = g_invS[b];
    const float* erow = &g_E[(long)b * VPAD];
    float* yrow = &out_y[((long)b * T + t) * VOCAB];
    for (int j = blockIdx.x * blockDim.x + threadIdx.x; j < VOCAB; j += gridDim.x * blockDim.x)
        yrow[j] = erow[j] * inv;
}

// ---------------- host launcher ----------------
extern "C" void kernel_launch(void* const* d_in, const int* in_sizes, int n_in,
                              void* d_out, int out_size) {
    const int*   x      = (const int*)d_in[0];
    const float* h_prev = (const float*)d_in[3];
    const float* emb    = (const float*)d_in[4];
    const float* U0     = (const float*)d_in[5];
    const float* W0     = (const float*)d_in[6];
    const float* b0     = (const float*)d_in[7];
    const float* V0     = (const float*)d_in[8];
    const float* c0     = (const float*)d_in[9];
    const float* U1     = (const float*)d_in[10];
    const float* W1     = (const float*)d_in[11];
    const float* b1     = (const float*)d_in[12];
    const float* V1     = (const float*)d_in[13];
    const float* c1     = (const float*)d_in[14];

    float* out = (float*)d_out;
    int T = out_size / (BB * (HH + VOCAB));
    float* out_h = out;
    float* out_y = out + (long)BB * T * HH;

    float *p_xcur, *p_h0, *p_h1, *p_x1;
    cudaGetSymbolAddress((void**)&p_xcur, g_xcur);
    cudaGetSymbolAddress((void**)&p_h0,   g_h0s);
    cudaGetSymbolAddress((void**)&p_h1,   g_h1s);
    cudaGetSymbolAddress((void**)&p_x1,   g_x1);

    const int SMEM_DUAL   = 37568 * 4;   // 150272 B
    const int SMEM_SINGLE = 18832 * 4;   // 75328 B
    cudaFuncSetAttribute(k_cellx<0>, cudaFuncAttributeMaxDynamicSharedMemorySize, SMEM_DUAL);
    cudaFuncSetAttribute(k_cellx<1>, cudaFuncAttributeMaxDynamicSharedMemorySize, SMEM_SINGLE);
    cudaFuncSetAttribute(k_cellx<2>, cudaFuncAttributeMaxDynamicSharedMemorySize, SMEM_DUAL);

    k_init<<<BB, 512>>>(x, h_prev, emb);
    k_pack_c1<<<(VPAD + 255) / 256, 256>>>(c1);
    k_pack_b<<<dim3(197, 32), 256>>>(V1);

    for (int t = 0; t < T; t++) {
        int cur = t & 1;
        float* h0c = p_h0 + cur * BB * HH;
        float* h0n = p_h0 + (cur ^ 1) * BB * HH;
        float* h1c = p_h1 + cur * BB * HH;
        float* h1n = p_h1 + (cur ^ 1) * BB * HH;

        // h0 = tanh(x@U0 + h0p@W0 + b0)
        k_cellx<0><<<128, 256, SMEM_DUAL>>>(p_xcur, h0c, U0, W0, b0, h0n, nullptr, 0, T);
        // e0 = exp(h0@V0 + c0) + row partials
        k_cellx<1><<<128, 256, SMEM_SINGLE>>>(h0n, nullptr, V0, nullptr, c0, nullptr, nullptr, 0, T);
        // x1 = tanh(e0 / S)
        k_sfm<<<BB, 256>>>(p_x1);
        // h1 = tanh(x1@U1 + h1p@W1 + b1) + out_h + frag pack
        k_cellx<2><<<128, 256, SMEM_DUAL>>>(p_x1, h1c, U1, W1, b1, h1n, out_h, t, T);
        // logits1 -> exp + partials
        k_big<<<NBLK, 256>>>();
        // invS + argmax + feedback embed
        k_comb<<<BB, 128>>>(emb);
        // y out
        k_writey<<<dim3(64, BB), 256>>>(out_y, t, T);
    }
}